// round 10
// baseline (speedup 1.0000x reference)
#include <cuda_runtime.h>
#include <cuda_bf16.h>

#define D 512
#define MAXC 512
#define MAXN 32768
#define NBLK 64
#define CHUNK 64

// Scratch (__device__ globals per allocation-free rule)
__device__ int   g_part[NBLK * MAXC];   // per-block class histograms [b][c]
__device__ int   g_offsets[MAXC + 1];   // class offsets into sorted row list
__device__ int   g_idx[MAXN];           // row offsets (i*D), grouped by class
__device__ int   g_cls[MAXN];           // class id per sorted position
__device__ float g_sum[2 * MAXC * D];   // per-(modal,class) partial sums
                                        // (zero at static init; epilogue re-zeroes)

// Grid barrier state. Self-restoring: g_barcnt reset by last arriver each
// barrier; g_sense flips per barrier and prep executes an EVEN number of
// barriers, so both return to 0 before every launch (graph-replay safe).
__device__ unsigned g_barcnt = 0;
__device__ volatile int g_sense = 0;

__device__ __forceinline__ void grid_barrier(int* s_sense) {
    __syncthreads();
    if (threadIdx.x == 0) {
        int target = 1 - *s_sense;
        *s_sense = target;
        __threadfence();
        unsigned prev = atomicAdd(&g_barcnt, 1u);
        if (prev == NBLK - 1) {
            g_barcnt = 0;
            __threadfence();
            g_sense = target;
        } else {
            while (g_sense != target) {}
        }
        __threadfence();
    }
    __syncthreads();
}

// ---------------------------------------------------------------------------
// Fused prep: histogram -> barrier -> scan -> scatter (idx + cls) -> barrier.
// Grid MUST be exactly NBLK blocks of MAXC threads (thread t owns class t).
__global__ void prep_kernel(const int* __restrict__ targets, int N,
                            float* __restrict__ out) {
    __shared__ int sh[MAXC];
    __shared__ int scur[MAXC];
    __shared__ int s_sense;
    int t = threadIdx.x;   // blockDim.x == MAXC
    int b = blockIdx.x;

    if (t == 0) s_sense = 0;
    sh[t] = 0;
    __syncthreads();

    // Phase 1: per-block histogram (smem atomics only)
    for (int i = b * MAXC + t; i < N; i += NBLK * MAXC)
        atomicAdd(&sh[targets[i]], 1);
    __syncthreads();
    g_part[b * MAXC + t] = sh[t];

    grid_barrier(&s_sense);

    // Phase 2: cross-block prefix for class t + class-offset scan
    int run = 0, total = 0;
    #pragma unroll
    for (int bb = 0; bb < NBLK; bb++) {
        int v = g_part[bb * MAXC + t];
        if (bb < b) run += v;
        total += v;
    }
    __syncthreads();
    sh[t] = total;
    __syncthreads();
    for (int off = 1; off < MAXC; off <<= 1) {
        int v = sh[t];
        int add = (t >= off) ? sh[t - off] : 0;
        __syncthreads();
        sh[t] = v + add;
        __syncthreads();
    }
    int excl = (t == 0) ? 0 : sh[t - 1];
    scur[t] = excl + run;
    if (b == 0) {
        g_offsets[t] = excl;
        if (t == MAXC - 1) g_offsets[MAXC] = sh[MAXC - 1];
        if (t == 0) out[0] = 0.0f;
    }
    __syncthreads();

    // Phase 3: scatter row offsets AND class ids (same mapping as phase 1)
    for (int i = b * MAXC + t; i < N; i += NBLK * MAXC) {
        int c = targets[i];
        int p = atomicAdd(&scur[c], 1);
        g_idx[p] = i * D;
        g_cls[p] = c;
    }

    grid_barrier(&s_sense);   // even count -> g_sense restored to 0
}

__device__ __forceinline__ void f4acc(float4& a, const float4 v) {
    a.x += v.x; a.y += v.y; a.z += v.z; a.w += v.w;
}

// ---------------------------------------------------------------------------
// Pass A: fixed-size chunk reduce. gridDim = (ceil(N/64), 2), blockDim = 128.
// Every CTA streams exactly 64 rows (2KB each) -> perfect load balance,
// single resident wave (8/SM * 148 = 1184 >= 1024 CTAs).
// Each thread owns one float4 column (128 threads cover D=512). Per-segment
// partial sums flush into g_sum via spread atomics (~2 collisions/address).
__global__ __launch_bounds__(128, 8)
void chunk_reduce_kernel(const float* __restrict__ m1,
                         const float* __restrict__ m2,
                         int N) {
    __shared__ int sidx[CHUNK];
    __shared__ int scls[CHUNK];
    __shared__ int sbeg[CHUNK + 1];
    __shared__ int s_wcnt[2];
    __shared__ int s_nseg;

    int tid = threadIdx.x;
    int base = blockIdx.x * CHUNK;
    int m = min(CHUNK, N - base);
    const float* __restrict__ data = blockIdx.y ? m2 : m1;
    float* __restrict__ sums = g_sum + (blockIdx.y ? MAXC * D : 0);

    // Stage indices (threads 0..63) + classes (threads 64..127)
    if (tid < m)                        sidx[tid] = g_idx[base + tid];
    if (tid >= 64 && tid - 64 < m)      scls[tid - 64] = g_cls[base + tid - 64];
    __syncthreads();

    // Segment detection, phase 1: per-warp break counts ONLY (no sbeg writes).
    if (tid < 64) {
        int flag = (tid < m) && (tid == 0 || scls[tid] != scls[tid - 1]);
        unsigned mask = __ballot_sync(0xffffffff, flag);
        if ((tid & 31) == 31) s_wcnt[tid >> 5] = __popc(mask);
    }
    __syncthreads();
    // Phase 2: deterministic sbeg writes with both warp counts visible.
    if (tid < 64) {
        int flag = (tid < m) && (tid == 0 || scls[tid] != scls[tid - 1]);
        unsigned mask = __ballot_sync(0xffffffff, flag);
        int lane = tid & 31;
        int segid = __popc(mask & ((1u << lane) - 1)) + ((tid >= 32) ? s_wcnt[0] : 0);
        if (flag) sbeg[segid] = tid;
        if (tid == 0) s_nseg = s_wcnt[0] + s_wcnt[1];
    }
    __syncthreads();
    if (tid == 0) sbeg[s_nseg] = m;
    __syncthreads();

    int nseg = s_nseg;
    for (int s = 0; s < nseg; s++) {
        int p0 = sbeg[s];
        int p1 = sbeg[s + 1];
        int c  = scls[p0];

        float4 a0 = make_float4(0.f,0.f,0.f,0.f), a1 = a0, a2 = a0, a3 = a0;
        float4 a4 = a0, a5 = a0, a6 = a0, a7 = a0;

        int j = p0;
        for (; j + 8 <= p1; j += 8) {
            f4acc(a0, __ldg((const float4*)(data + sidx[j])     + tid));
            f4acc(a1, __ldg((const float4*)(data + sidx[j + 1]) + tid));
            f4acc(a2, __ldg((const float4*)(data + sidx[j + 2]) + tid));
            f4acc(a3, __ldg((const float4*)(data + sidx[j + 3]) + tid));
            f4acc(a4, __ldg((const float4*)(data + sidx[j + 4]) + tid));
            f4acc(a5, __ldg((const float4*)(data + sidx[j + 5]) + tid));
            f4acc(a6, __ldg((const float4*)(data + sidx[j + 6]) + tid));
            f4acc(a7, __ldg((const float4*)(data + sidx[j + 7]) + tid));
        }
        for (; j < p1; j++)
            f4acc(a0, __ldg((const float4*)(data + sidx[j]) + tid));

        f4acc(a0, a1); f4acc(a2, a3); f4acc(a4, a5); f4acc(a6, a7);
        f4acc(a0, a2); f4acc(a4, a6); f4acc(a0, a4);

        float* dst = sums + c * D + tid * 4;
        atomicAdd(dst + 0, a0.x);
        atomicAdd(dst + 1, a0.y);
        atomicAdd(dst + 2, a0.z);
        atomicAdd(dst + 3, a0.w);
    }
}

// ---------------------------------------------------------------------------
// Pass B: epilogue. gridDim = (C, 2), blockDim = 128. Reads g_sum, computes
// smooth-L1 vs centers weighted by count, atomically accumulates into out.
// Re-zeroes g_sum behind itself so scratch state is identical every replay.
__global__ void epilogue_kernel(const float* __restrict__ centers,
                                float* __restrict__ out,
                                float inv_nd) {
    __shared__ float swarp[4];
    int c   = blockIdx.x;
    int tid = threadIdx.x;
    float* sums = g_sum + (blockIdx.y ? MAXC * D : 0) + c * D;

    int cnt = g_offsets[c + 1] - g_offsets[c];
    float4 s = *(float4*)(sums + tid * 4);
    // self-clean for next replay
    *(float4*)(sums + tid * 4) = make_float4(0.f, 0.f, 0.f, 0.f);

    float v = 0.0f;
    if (cnt > 0) {
        float inv_cnt = 1.0f / (float)cnt;
        float4 ctr = __ldg((const float4*)(centers + c * D) + tid);
        float dx = fabsf(s.x * inv_cnt - ctr.x);
        float dy = fabsf(s.y * inv_cnt - ctr.y);
        float dz = fabsf(s.z * inv_cnt - ctr.z);
        float dw = fabsf(s.w * inv_cnt - ctr.w);
        float l = ((dx < 1.f) ? 0.5f * dx * dx : dx - 0.5f)
                + ((dy < 1.f) ? 0.5f * dy * dy : dy - 0.5f)
                + ((dz < 1.f) ? 0.5f * dz * dz : dz - 0.5f)
                + ((dw < 1.f) ? 0.5f * dw * dw : dw - 0.5f);
        v = l * (float)cnt;
    }

    #pragma unroll
    for (int o = 16; o; o >>= 1) v += __shfl_xor_sync(0xffffffff, v, o);
    if ((tid & 31) == 0) swarp[tid >> 5] = v;
    __syncthreads();
    if (tid < 32) {
        float w = (tid < 4) ? swarp[tid] : 0.0f;
        #pragma unroll
        for (int o = 2; o; o >>= 1) w += __shfl_xor_sync(0xffffffff, w, o);
        if (tid == 0) atomicAdd(out, w * inv_nd);
    }
}

// ---------------------------------------------------------------------------
extern "C" void kernel_launch(void* const* d_in, const int* in_sizes, int n_in,
                              void* d_out, int out_size) {
    const float* m1      = (const float*)d_in[0];  // modal1_inputs [N, 512]
    const float* m2      = (const float*)d_in[1];  // modal2_inputs [N, 512]
    const float* centers = (const float*)d_in[2];  // centers [C, 512]
    const int*   targets = (const int*)d_in[3];    // targets [N]

    int N = in_sizes[3];
    int C = in_sizes[2] / D;
    float* out = (float*)d_out;
    float inv_nd = 1.0f / ((float)N * (float)D);

    prep_kernel<<<NBLK, MAXC>>>(targets, N, out);

    int nchunk = (N + CHUNK - 1) / CHUNK;
    dim3 gridA(nchunk, 2);
    chunk_reduce_kernel<<<gridA, 128>>>(m1, m2, N);

    dim3 gridB(C, 2);
    epilogue_kernel<<<gridB, 128>>>(centers, out, inv_nd);
}

// round 12
// speedup vs baseline: 1.0977x; 1.0977x over previous
#include <cuda_runtime.h>
#include <cuda_bf16.h>

#define D 512
#define MAXC 512
#define MAXN 32768
#define NBLK 64
#define CHUNK 64

// Scratch (__device__ globals per allocation-free rule)
__device__ int   g_part[NBLK * MAXC];   // per-block class histograms [b][c]
__device__ int   g_offsets[MAXC + 1];   // class offsets into sorted row list
__device__ int   g_idx[MAXN];           // packed (row*512 | class), sorted by class
__device__ int   g_rem[2 * MAXC];       // per-(modal,class) pending chunk flushes
__device__ float g_sum[2 * MAXC * D];   // per-(modal,class) partial sums
                                        // (zero at static init; last owner re-zeroes)

// Grid barrier. g_sense parity persists across launches: each block reads the
// current value at kernel start, so one barrier per launch is fine.
__device__ unsigned g_barcnt = 0;
__device__ volatile int g_sense = 0;

__device__ __forceinline__ void grid_barrier(int* s_sense) {
    __syncthreads();
    if (threadIdx.x == 0) {
        int target = 1 - *s_sense;
        *s_sense = target;
        __threadfence();
        unsigned prev = atomicAdd(&g_barcnt, 1u);
        if (prev == NBLK - 1) {
            g_barcnt = 0;
            __threadfence();
            g_sense = target;
        } else {
            while (g_sense != target) {}
        }
        __threadfence();
    }
    __syncthreads();
}

// ---------------------------------------------------------------------------
// Fused prep: histogram -> barrier -> scan -> scatter packed (idx|cls).
// Grid MUST be exactly NBLK blocks of MAXC threads (thread t owns class t).
__global__ void prep_kernel(const int* __restrict__ targets, int N,
                            float* __restrict__ out) {
    __shared__ int sh[MAXC];
    __shared__ int scur[MAXC];
    __shared__ int s_sense;
    int t = threadIdx.x;   // blockDim.x == MAXC
    int b = blockIdx.x;

    if (t == 0) s_sense = g_sense;   // inherit persisted parity
    sh[t] = 0;
    __syncthreads();

    // Phase 1: per-block histogram (smem atomics only)
    for (int i = b * MAXC + t; i < N; i += NBLK * MAXC)
        atomicAdd(&sh[targets[i]], 1);
    __syncthreads();
    g_part[b * MAXC + t] = sh[t];

    grid_barrier(&s_sense);   // the ONLY grid barrier this kernel executes

    // Phase 2: cross-block prefix for class t + class-offset scan
    int run = 0, total = 0;
    #pragma unroll
    for (int bb = 0; bb < NBLK; bb++) {
        int v = g_part[bb * MAXC + t];
        if (bb < b) run += v;
        total += v;
    }
    __syncthreads();
    sh[t] = total;
    __syncthreads();
    for (int off = 1; off < MAXC; off <<= 1) {
        int v = sh[t];
        int add = (t >= off) ? sh[t - off] : 0;
        __syncthreads();
        sh[t] = v + add;
        __syncthreads();
    }
    int excl = (t == 0) ? 0 : sh[t - 1];
    scur[t] = excl + run;
    if (b == 0) {
        g_offsets[t] = excl;
        if (t == MAXC - 1) g_offsets[MAXC] = sh[MAXC - 1];
        if (t == 0) out[0] = 0.0f;
        // Pending-flush count for class t = #chunks overlapping [excl, excl+total)
        int rem = (total > 0) ? ((excl + total - 1) / CHUNK) - (excl / CHUNK) + 1 : 0;
        g_rem[t]        = rem;   // modal 0
        g_rem[MAXC + t] = rem;   // modal 1
    }
    __syncthreads();

    // Phase 3: scatter packed (row*512 | class). Same mapping as phase 1.
    for (int i = b * MAXC + t; i < N; i += NBLK * MAXC) {
        int c = targets[i];
        int p = atomicAdd(&scur[c], 1);
        g_idx[p] = (i << 9) | c;   // i*D has 9 zero low bits; c < 512
    }
    // Visibility to the next kernel is guaranteed by launch ordering.
}

__device__ __forceinline__ void f4acc(float4& a, const float4 v) {
    a.x += v.x; a.y += v.y; a.z += v.z; a.w += v.w;
}

// ---------------------------------------------------------------------------
// Pass A (+fused epilogue): fixed-size chunk reduce.
// gridDim = (N/64, 2), blockDim = 128. Every CTA streams exactly 64 rows
// (2KB each) -> perfect balance, single resident wave (8/SM*148=1184 >= 1024).
// Each thread owns one float4 column. Per-segment sums flush into g_sum with
// spread atomics; the LAST flusher of each (modal,class) computes the
// smooth-L1 contribution and re-zeroes g_sum (self-cleaning for graph replay).
__global__ __launch_bounds__(128, 8)
void chunk_reduce_kernel(const float* __restrict__ m1,
                         const float* __restrict__ m2,
                         const float* __restrict__ centers,
                         float* __restrict__ out,
                         float inv_nd, int N) {
    __shared__ int sidx[CHUNK];       // packed entries
    __shared__ short scls[CHUNK];
    __shared__ int sbeg[CHUNK + 1];
    __shared__ int s_wcnt[2];
    __shared__ int s_nseg;
    __shared__ int s_last;
    __shared__ float swarp[4];

    int tid = threadIdx.x;
    int base = blockIdx.x * CHUNK;
    int m = min(CHUNK, N - base);
    int modal = blockIdx.y;
    const float* __restrict__ data = modal ? m2 : m1;
    float* __restrict__ sums = g_sum + (modal ? MAXC * D : 0);
    int* __restrict__ rem = g_rem + (modal ? MAXC : 0);

    // Stage packed entries
    if (tid < m) {
        int p = g_idx[base + tid];
        sidx[tid] = p;
        scls[tid] = (short)(p & 0x1FF);
    }
    __syncthreads();

    // Segment detection (threads 0..63). Phase 1: per-warp break counts only.
    if (tid < 64) {
        int flag = (tid < m) && (tid == 0 || scls[tid] != scls[tid - 1]);
        unsigned mask = __ballot_sync(0xffffffff, flag);
        if ((tid & 31) == 31) s_wcnt[tid >> 5] = __popc(mask);
    }
    __syncthreads();
    // Phase 2: deterministic sbeg writes with both warp counts visible.
    if (tid < 64) {
        int flag = (tid < m) && (tid == 0 || scls[tid] != scls[tid - 1]);
        unsigned mask = __ballot_sync(0xffffffff, flag);
        int lane = tid & 31;
        int segid = __popc(mask & ((1u << lane) - 1)) + ((tid >= 32) ? s_wcnt[0] : 0);
        if (flag) sbeg[segid] = tid;
        if (tid == 0) s_nseg = s_wcnt[0] + s_wcnt[1];
    }
    __syncthreads();
    if (tid == 0) sbeg[s_nseg] = m;
    __syncthreads();

    int nseg = s_nseg;
    for (int s = 0; s < nseg; s++) {
        int p0 = sbeg[s];
        int p1 = sbeg[s + 1];
        int c  = (int)scls[p0];

        float4 a0 = make_float4(0.f,0.f,0.f,0.f), a1 = a0, a2 = a0, a3 = a0;
        float4 a4 = a0, a5 = a0, a6 = a0, a7 = a0;

        int j = p0;
        for (; j + 8 <= p1; j += 8) {
            f4acc(a0, __ldcs((const float4*)(data + (sidx[j]     & ~0x1FF)) + tid));
            f4acc(a1, __ldcs((const float4*)(data + (sidx[j + 1] & ~0x1FF)) + tid));
            f4acc(a2, __ldcs((const float4*)(data + (sidx[j + 2] & ~0x1FF)) + tid));
            f4acc(a3, __ldcs((const float4*)(data + (sidx[j + 3] & ~0x1FF)) + tid));
            f4acc(a4, __ldcs((const float4*)(data + (sidx[j + 4] & ~0x1FF)) + tid));
            f4acc(a5, __ldcs((const float4*)(data + (sidx[j + 5] & ~0x1FF)) + tid));
            f4acc(a6, __ldcs((const float4*)(data + (sidx[j + 6] & ~0x1FF)) + tid));
            f4acc(a7, __ldcs((const float4*)(data + (sidx[j + 7] & ~0x1FF)) + tid));
        }
        for (; j < p1; j++)
            f4acc(a0, __ldcs((const float4*)(data + (sidx[j] & ~0x1FF)) + tid));

        f4acc(a0, a1); f4acc(a2, a3); f4acc(a4, a5); f4acc(a6, a7);
        f4acc(a0, a2); f4acc(a4, a6); f4acc(a0, a4);

        float* dst = sums + c * D + tid * 4;
        atomicAdd(dst + 0, a0.x);
        atomicAdd(dst + 1, a0.y);
        atomicAdd(dst + 2, a0.z);
        atomicAdd(dst + 3, a0.w);

        // Last-owner epilogue (canonical fence -> sync -> ticket pattern)
        __threadfence();
        __syncthreads();
        if (tid == 0) s_last = (atomicSub(&rem[c], 1) == 1);
        __syncthreads();
        if (s_last) {
            int cnt = g_offsets[c + 1] - g_offsets[c];
            float inv_cnt = 1.0f / (float)cnt;
            float* sp = sums + c * D + tid * 4;
            float4 sv = __ldcg((const float4*)sp);   // L2 read: sees all flushes
            // self-clean for next replay
            *(float4*)sp = make_float4(0.f, 0.f, 0.f, 0.f);

            float4 ctr = __ldg((const float4*)(centers + c * D) + tid);
            float dx = fabsf(sv.x * inv_cnt - ctr.x);
            float dy = fabsf(sv.y * inv_cnt - ctr.y);
            float dz = fabsf(sv.z * inv_cnt - ctr.z);
            float dw = fabsf(sv.w * inv_cnt - ctr.w);
            float l = ((dx < 1.f) ? 0.5f * dx * dx : dx - 0.5f)
                    + ((dy < 1.f) ? 0.5f * dy * dy : dy - 0.5f)
                    + ((dz < 1.f) ? 0.5f * dz * dz : dz - 0.5f)
                    + ((dw < 1.f) ? 0.5f * dw * dw : dw - 0.5f);
            float v = l * (float)cnt;

            #pragma unroll
            for (int o = 16; o; o >>= 1) v += __shfl_xor_sync(0xffffffff, v, o);
            if ((tid & 31) == 0) swarp[tid >> 5] = v;
            __syncthreads();
            if (tid < 32) {
                float w = (tid < 4) ? swarp[tid] : 0.0f;
                #pragma unroll
                for (int o = 2; o; o >>= 1) w += __shfl_xor_sync(0xffffffff, w, o);
                if (tid == 0) atomicAdd(out, w * inv_nd);
            }
        }
        __syncthreads();   // protect smem (swarp/s_last) across segments
    }
}

// ---------------------------------------------------------------------------
extern "C" void kernel_launch(void* const* d_in, const int* in_sizes, int n_in,
                              void* d_out, int out_size) {
    const float* m1      = (const float*)d_in[0];  // modal1_inputs [N, 512]
    const float* m2      = (const float*)d_in[1];  // modal2_inputs [N, 512]
    const float* centers = (const float*)d_in[2];  // centers [C, 512]
    const int*   targets = (const int*)d_in[3];    // targets [N]

    int N = in_sizes[3];
    float* out = (float*)d_out;
    float inv_nd = 1.0f / ((float)N * (float)D);

    prep_kernel<<<NBLK, MAXC>>>(targets, N, out);

    int nchunk = (N + CHUNK - 1) / CHUNK;
    dim3 gridA(nchunk, 2);
    chunk_reduce_kernel<<<gridA, 128>>>(m1, m2, centers, out, inv_nd, N);
}

// round 13
// speedup vs baseline: 1.1089x; 1.0102x over previous
#include <cuda_runtime.h>
#include <cuda_bf16.h>

#define D 512
#define MAXC 512
#define MAXN 32768
#define NBLK 64
#define CHUNK 64

// Scratch (__device__ globals per allocation-free rule)
__device__ int   g_part[NBLK * MAXC];   // per-block class histograms [b][c]
__device__ int   g_offsets[MAXC + 1];   // class offsets into sorted row list
__device__ int   g_idx[MAXN];           // packed (row*512 | class), sorted by class
__device__ int   g_rem[2 * MAXC];       // per-(modal,class) pending chunk flushes
__device__ float g_sum[2 * MAXC * D];   // per-(modal,class) partial sums
                                        // (zero at static init; last owner re-zeroes)

// Grid barrier. g_sense parity persists across launches: each block reads the
// current value at kernel start, so one barrier per launch is fine.
__device__ unsigned g_barcnt = 0;
__device__ volatile int g_sense = 0;

__device__ __forceinline__ void grid_barrier(int* s_sense) {
    __syncthreads();
    if (threadIdx.x == 0) {
        int target = 1 - *s_sense;
        *s_sense = target;
        __threadfence();
        unsigned prev = atomicAdd(&g_barcnt, 1u);
        if (prev == NBLK - 1) {
            g_barcnt = 0;
            __threadfence();
            g_sense = target;
        } else {
            while (g_sense != target) {}
        }
        __threadfence();
    }
    __syncthreads();
}

// ---------------------------------------------------------------------------
// Fused prep: histogram -> barrier -> scan -> scatter packed (idx|cls).
// Grid MUST be exactly NBLK blocks of MAXC threads (thread t owns class t).
__global__ void prep_kernel(const int* __restrict__ targets, int N,
                            float* __restrict__ out) {
    __shared__ int sh[MAXC];
    __shared__ int scur[MAXC];
    __shared__ int s_sense;
    int t = threadIdx.x;   // blockDim.x == MAXC
    int b = blockIdx.x;

    if (t == 0) s_sense = g_sense;   // inherit persisted parity
    sh[t] = 0;
    __syncthreads();

    // Phase 1: per-block histogram (smem atomics only)
    for (int i = b * MAXC + t; i < N; i += NBLK * MAXC)
        atomicAdd(&sh[targets[i]], 1);
    __syncthreads();
    g_part[b * MAXC + t] = sh[t];

    grid_barrier(&s_sense);   // the ONLY grid barrier this kernel executes

    // Phase 2: cross-block prefix for class t + class-offset scan
    int run = 0, total = 0;
    #pragma unroll
    for (int bb = 0; bb < NBLK; bb++) {
        int v = g_part[bb * MAXC + t];
        if (bb < b) run += v;
        total += v;
    }
    __syncthreads();
    sh[t] = total;
    __syncthreads();
    for (int off = 1; off < MAXC; off <<= 1) {
        int v = sh[t];
        int add = (t >= off) ? sh[t - off] : 0;
        __syncthreads();
        sh[t] = v + add;
        __syncthreads();
    }
    int excl = (t == 0) ? 0 : sh[t - 1];
    scur[t] = excl + run;
    if (b == 0) {
        g_offsets[t] = excl;
        if (t == MAXC - 1) g_offsets[MAXC] = sh[MAXC - 1];
        if (t == 0) out[0] = 0.0f;
        // Pending-flush count for class t = #chunks overlapping [excl, excl+total)
        int rem = (total > 0) ? ((excl + total - 1) / CHUNK) - (excl / CHUNK) + 1 : 0;
        g_rem[t]        = rem;   // modal 0
        g_rem[MAXC + t] = rem;   // modal 1
    }
    __syncthreads();

    // Phase 3: scatter packed (row*512 | class). Same mapping as phase 1.
    for (int i = b * MAXC + t; i < N; i += NBLK * MAXC) {
        int c = targets[i];
        int p = atomicAdd(&scur[c], 1);
        g_idx[p] = (i << 9) | c;   // i*D has 9 zero low bits; c < 512
    }
    // Visibility to the next kernel is guaranteed by launch ordering.
}

__device__ __forceinline__ void f4acc(float4& a, const float4 v) {
    a.x += v.x; a.y += v.y; a.z += v.z; a.w += v.w;
}

// ---------------------------------------------------------------------------
// Pass A (+fused epilogue): fixed-size chunk reduce.
// gridDim = (N/64, 2), blockDim = 128. Every CTA streams exactly 64 rows
// (2KB each) -> perfect balance, single resident wave (8/SM*148=1184 >= 1024).
// Each thread owns one float4 column. Per-segment sums flush into g_sum with
// spread atomics; the LAST flusher of each (modal,class) computes the
// smooth-L1 contribution and re-zeroes g_sum (self-cleaning for graph replay).
__global__ __launch_bounds__(128, 8)
void chunk_reduce_kernel(const float* __restrict__ m1,
                         const float* __restrict__ m2,
                         const float* __restrict__ centers,
                         float* __restrict__ out,
                         float inv_nd, int N) {
    __shared__ int sidx[CHUNK];       // packed entries
    __shared__ short scls[CHUNK];
    __shared__ int sbeg[CHUNK + 1];
    __shared__ int s_wcnt[2];
    __shared__ int s_nseg;
    __shared__ int s_last;
    __shared__ float swarp[4];

    int tid = threadIdx.x;
    int base = blockIdx.x * CHUNK;
    int m = min(CHUNK, N - base);
    int modal = blockIdx.y;
    const float* __restrict__ data = modal ? m2 : m1;
    float* __restrict__ sums = g_sum + (modal ? MAXC * D : 0);
    int* __restrict__ rem = g_rem + (modal ? MAXC : 0);

    // Stage packed entries
    if (tid < m) {
        int p = g_idx[base + tid];
        sidx[tid] = p;
        scls[tid] = (short)(p & 0x1FF);
    }
    __syncthreads();

    // Segment detection (threads 0..63). Phase 1: per-warp break counts only.
    if (tid < 64) {
        int flag = (tid < m) && (tid == 0 || scls[tid] != scls[tid - 1]);
        unsigned mask = __ballot_sync(0xffffffff, flag);
        if ((tid & 31) == 31) s_wcnt[tid >> 5] = __popc(mask);
    }
    __syncthreads();
    // Phase 2: deterministic sbeg writes with both warp counts visible.
    if (tid < 64) {
        int flag = (tid < m) && (tid == 0 || scls[tid] != scls[tid - 1]);
        unsigned mask = __ballot_sync(0xffffffff, flag);
        int lane = tid & 31;
        int segid = __popc(mask & ((1u << lane) - 1)) + ((tid >= 32) ? s_wcnt[0] : 0);
        if (flag) sbeg[segid] = tid;
        if (tid == 0) s_nseg = s_wcnt[0] + s_wcnt[1];
    }
    __syncthreads();
    if (tid == 0) sbeg[s_nseg] = m;
    __syncthreads();

    int nseg = s_nseg;
    for (int s = 0; s < nseg; s++) {
        int p0 = sbeg[s];
        int p1 = sbeg[s + 1];
        int c  = (int)scls[p0];

        float4 a0 = make_float4(0.f,0.f,0.f,0.f), a1 = a0, a2 = a0, a3 = a0;
        float4 a4 = a0, a5 = a0, a6 = a0, a7 = a0;

        int j = p0;
        for (; j + 8 <= p1; j += 8) {
            f4acc(a0, __ldcs((const float4*)(data + (sidx[j]     & ~0x1FF)) + tid));
            f4acc(a1, __ldcs((const float4*)(data + (sidx[j + 1] & ~0x1FF)) + tid));
            f4acc(a2, __ldcs((const float4*)(data + (sidx[j + 2] & ~0x1FF)) + tid));
            f4acc(a3, __ldcs((const float4*)(data + (sidx[j + 3] & ~0x1FF)) + tid));
            f4acc(a4, __ldcs((const float4*)(data + (sidx[j + 4] & ~0x1FF)) + tid));
            f4acc(a5, __ldcs((const float4*)(data + (sidx[j + 5] & ~0x1FF)) + tid));
            f4acc(a6, __ldcs((const float4*)(data + (sidx[j + 6] & ~0x1FF)) + tid));
            f4acc(a7, __ldcs((const float4*)(data + (sidx[j + 7] & ~0x1FF)) + tid));
        }
        for (; j < p1; j++)
            f4acc(a0, __ldcs((const float4*)(data + (sidx[j] & ~0x1FF)) + tid));

        f4acc(a0, a1); f4acc(a2, a3); f4acc(a4, a5); f4acc(a6, a7);
        f4acc(a0, a2); f4acc(a4, a6); f4acc(a0, a4);

        float* dst = sums + c * D + tid * 4;
        atomicAdd(dst + 0, a0.x);
        atomicAdd(dst + 1, a0.y);
        atomicAdd(dst + 2, a0.z);
        atomicAdd(dst + 3, a0.w);

        // Last-owner epilogue (canonical fence -> sync -> ticket pattern)
        __threadfence();
        __syncthreads();
        if (tid == 0) s_last = (atomicSub(&rem[c], 1) == 1);
        __syncthreads();
        if (s_last) {
            int cnt = g_offsets[c + 1] - g_offsets[c];
            float inv_cnt = 1.0f / (float)cnt;
            float* sp = sums + c * D + tid * 4;
            float4 sv = __ldcg((const float4*)sp);   // L2 read: sees all flushes
            // self-clean for next replay
            *(float4*)sp = make_float4(0.f, 0.f, 0.f, 0.f);

            float4 ctr = __ldg((const float4*)(centers + c * D) + tid);
            float dx = fabsf(sv.x * inv_cnt - ctr.x);
            float dy = fabsf(sv.y * inv_cnt - ctr.y);
            float dz = fabsf(sv.z * inv_cnt - ctr.z);
            float dw = fabsf(sv.w * inv_cnt - ctr.w);
            float l = ((dx < 1.f) ? 0.5f * dx * dx : dx - 0.5f)
                    + ((dy < 1.f) ? 0.5f * dy * dy : dy - 0.5f)
                    + ((dz < 1.f) ? 0.5f * dz * dz : dz - 0.5f)
                    + ((dw < 1.f) ? 0.5f * dw * dw : dw - 0.5f);
            float v = l * (float)cnt;

            #pragma unroll
            for (int o = 16; o; o >>= 1) v += __shfl_xor_sync(0xffffffff, v, o);
            if ((tid & 31) == 0) swarp[tid >> 5] = v;
            __syncthreads();
            if (tid < 32) {
                float w = (tid < 4) ? swarp[tid] : 0.0f;
                #pragma unroll
                for (int o = 2; o; o >>= 1) w += __shfl_xor_sync(0xffffffff, w, o);
                if (tid == 0) atomicAdd(out, w * inv_nd);
            }
        }
        __syncthreads();   // protect smem (swarp/s_last) across segments
    }
}

// ---------------------------------------------------------------------------
extern "C" void kernel_launch(void* const* d_in, const int* in_sizes, int n_in,
                              void* d_out, int out_size) {
    const float* m1      = (const float*)d_in[0];  // modal1_inputs [N, 512]
    const float* m2      = (const float*)d_in[1];  // modal2_inputs [N, 512]
    const float* centers = (const float*)d_in[2];  // centers [C, 512]
    const int*   targets = (const int*)d_in[3];    // targets [N]

    int N = in_sizes[3];
    float* out = (float*)d_out;
    float inv_nd = 1.0f / ((float)N * (float)D);

    prep_kernel<<<NBLK, MAXC>>>(targets, N, out);

    int nchunk = (N + CHUNK - 1) / CHUNK;
    dim3 gridA(nchunk, 2);
    chunk_reduce_kernel<<<gridA, 128>>>(m1, m2, centers, out, inv_nd, N);
}